// round 16
// baseline (speedup 1.0000x reference)
#include <cuda_runtime.h>
#include <cuda_bf16.h>
#include <cuda_fp16.h>
#include <cstdint>
#include <math.h>

#define N_USERS 50000
#define N_NODES 100000
#define D       64
#define BATCH   2048
#define NJ      50000
#define NT_N    ((NJ + 127) / 128)
#define NCH     18                           // 18*8*2 = 288 blocks = one wave @ 2 blocks/SM
#define PER_CH  ((NT_N + NCH - 1) / NCH)     // 22
#define K2EXP   2.885390081777927f           // 2/ln(2)

// ---------------- device scratch (zero-init; invariants restored every run) ----------------
__device__ __align__(16) __nv_bfloat16 g_egoh[N_NODES * D];
__device__ __align__(16) float g_e1 [N_NODES * D];
__device__ __align__(16) __nv_bfloat16 g_e2b[N_NODES * D];
__device__ __align__(16) __nv_bfloat16 g_e2h[N_NODES * D];
__device__ __align__(16) __nv_bfloat16 g_z1h[2 * BATCH * D];
__device__ float g_dot[2 * BATCH];
__device__ float g_ttl[2 * BATCH];            // zeroed by k_final
__device__ unsigned g_bitmap[(N_NODES + 31) / 32];  // cleared by k_norm_sample
__device__ int g_qn;                          // reset by k_norm_sample
__device__ int g_queue[2000000];

__device__ __forceinline__ uint32_t swz(uint32_t o) { return o ^ ((o >> 3) & 0x70); }
__device__ __forceinline__ uint32_t su32(const void* p) {
    uint32_t a;
    asm("{ .reg .u64 t; cvta.to.shared.u64 t, %1; cvt.u32.u64 %0, t; }" : "=r"(a) : "l"(p));
    return a;
}
__device__ __forceinline__ uint32_t packh2(float hi, float lo) {
    uint32_t r; asm("cvt.rn.f16x2.f32 %0, %1, %2;" : "=r"(r) : "f"(hi), "f"(lo)); return r;
}
__device__ __forceinline__ uint32_t ex2h2(uint32_t x) {
    uint32_t r; asm("ex2.approx.f16x2 %0, %1;" : "=r"(r) : "r"(x)); return r;
}
__device__ __forceinline__ uint32_t haddh2(uint32_t a, uint32_t b) {
    uint32_t r; asm("add.rn.f16x2 %0, %1, %2;" : "=r"(r) : "r"(a), "r"(b)); return r;
}
__device__ __forceinline__ uint32_t packbf2(float lo, float hi) {
    __nv_bfloat162 h = __float22bfloat162_rn(make_float2(lo, hi));
    return *(uint32_t*)&h;
}
__device__ __forceinline__ uint32_t mulbf2(uint32_t a, uint32_t b) {
    uint32_t r; asm("mul.rn.bf16x2 %0, %1, %2;" : "=r"(r) : "r"(a), "r"(b)); return r;
}
__device__ __forceinline__ float4 gatherh(int node, int l) {
    uint2 u = *(const uint2*)&g_egoh[node * D + l * 4];
    float2 fa = __bfloat1622float2(*(__nv_bfloat162*)&u.x);
    float2 fb = __bfloat1622float2(*(__nv_bfloat162*)&u.y);
    return make_float4(fa.x, fa.y, fb.x, fb.y);
}
#define CP16(dst, src) \
    asm volatile("cp.async.ca.shared.global [%0], [%1], 16;" :: "r"(dst), "l"(src))
#define CP_COMMIT() asm volatile("cp.async.commit_group;")
#define CP_WAIT0()  asm volatile("cp.async.wait_group 0;")
#define REDV4(p, a, b, c, d) \
    asm volatile("red.global.add.v4.f32 [%0], {%1,%2,%3,%4};" \
                 :: "l"(p), "f"(a), "f"(b), "f"(c), "f"(d) : "memory")
#define REDBF8(p, r0, r1, r2, r3) \
    asm volatile("red.global.add.noftz.v4.bf16x2 [%0], {%1,%2,%3,%4};" \
                 :: "l"(p), "r"(r0), "r"(r1), "r"(r2), "r"(r3) : "memory")

// ---------------- setup: seed e1 at sampled rows + mark bitmap ----------------
__global__ void k_setup(const float* __restrict__ ue, const float* __restrict__ ie,
                        const int* __restrict__ nu, const int* __restrict__ ni) {
    int t = blockIdx.x * blockDim.x + threadIdx.x;
    int s = t >> 4, l = t & 15;
    if (s >= 2 * BATCH) return;
    int b = s & (BATCH - 1);
    int row; const float* src;
    if (s < BATCH) { row = nu[b];                 src = &ue[(size_t)row * D]; }
    else           { int r = ni[b]; row = N_USERS + r; src = &ie[(size_t)r * D]; }
    if (l == 0) atomicOr(&g_bitmap[row >> 5], 1u << (row & 31));
    float4 v = *(const float4*)&src[l * 4];
    *(float4*)&g_e1[(size_t)row * D + l * 4] =
        make_float4(0.5f * v.x, 0.5f * v.y, 0.5f * v.z, 0.5f * v.w);
}

// ---------------- init: g_e2b = bf16(0.5*ego), g_egoh = bf16(ego) ----------------
__global__ void k_init(const float* __restrict__ ue, const float* __restrict__ ie) {
    int i = blockIdx.x * blockDim.x + threadIdx.x;
    if (i >= N_NODES * D / 4) return;
    float4 v = (i < N_USERS * D / 4) ? ((const float4*)ue)[i]
                                     : ((const float4*)ie)[i - N_USERS * D / 4];
    uint2 h;
    h.x = packbf2(v.x, v.y);
    h.y = packbf2(v.z, v.w);
    ((uint2*)g_egoh)[i] = h;
    uint2 e;
    e.x = packbf2(0.5f * v.x, 0.5f * v.y);
    e.y = packbf2(0.5f * v.z, 0.5f * v.w);
    ((uint2*)g_e2b)[i] = e;
}

// ---------------- filtered SpMM-1: 16 edges/thread filter ----------------
__global__ void k_filter(const int* __restrict__ rows, int nnz) {
    int i0 = (blockIdx.x * blockDim.x + threadIdx.x) * 16;
    int lane = threadIdx.x & 31;
    int ids[16];
    int cnt = 0;
    if (i0 + 15 < nnz) {
        int4 ra = *(const int4*)&rows[i0];
        int4 rb = *(const int4*)&rows[i0 + 4];
        int4 rc = *(const int4*)&rows[i0 + 8];
        int4 rd = *(const int4*)&rows[i0 + 12];
        int rr[16] = {ra.x, ra.y, ra.z, ra.w, rb.x, rb.y, rb.z, rb.w,
                      rc.x, rc.y, rc.z, rc.w, rd.x, rd.y, rd.z, rd.w};
        #pragma unroll
        for (int j = 0; j < 16; j++)
            if ((g_bitmap[rr[j] >> 5] >> (rr[j] & 31)) & 1u) ids[cnt++] = i0 + j;
    } else {
        for (int j = 0; j < 16 && i0 + j < nnz; j++) {
            int rr = rows[i0 + j];
            if ((g_bitmap[rr >> 5] >> (rr & 31)) & 1u) ids[cnt++] = i0 + j;
        }
    }
    int x = cnt;
    #pragma unroll
    for (int o = 1; o < 32; o <<= 1) {
        int y = __shfl_up_sync(0xffffffffu, x, o);
        if (lane >= o) x += y;
    }
    int pre = x - cnt;
    int total = __shfl_sync(0xffffffffu, x, 31);
    int base = 0;
    if (lane == 31 && total) base = atomicAdd(&g_qn, total);
    base = __shfl_sync(0xffffffffu, base, 31);
    for (int j = 0; j < cnt; j++) g_queue[base + pre + j] = ids[j];
}

__global__ void k_spmm_q(const int* __restrict__ rows, const int* __restrict__ cols,
                         const float* __restrict__ vals) {
    int total = g_qn * 16;
    for (int t = blockIdx.x * blockDim.x + threadIdx.x; t < total;
         t += gridDim.x * blockDim.x) {
        int e = g_queue[t >> 4];
        int l = t & 15;
        int r = rows[e], c = cols[e];
        float v = 0.5f * vals[e];
        float4 x = gatherh(c, l);
        float* p = &g_e1[r * D + l * 4];
        REDV4(p, v * x.x, v * x.y, v * x.z, v * x.w);
    }
}

// ---------------- SpMM-2: interaction-paired, 8 lanes/interaction, v4.bf16x2 REDs ----------------
__global__ void k_spmm2(const int* __restrict__ rows, const int* __restrict__ cols,
                        const float* __restrict__ vals, int half) {
    unsigned t = blockIdx.x * blockDim.x + threadIdx.x;
    int q = (half + 3) >> 2;
    int p0 = (int)(t >> 3);
    int l = (int)(t & 7);
    if (p0 >= q) return;

    int pp[4] = {p0, p0 + q, p0 + 2 * q, p0 + 3 * q};
    int rr[4], cc[4];
    uint32_t vb[4];
    #pragma unroll
    for (int j = 0; j < 4; j++) {
        bool ok = pp[j] < half;
        int e = ok ? pp[j] : 0;
        rr[j] = __ldg(&rows[e]);
        cc[j] = __ldg(&cols[e]);
        float v = ok ? 0.5f * __ldg(&vals[e]) : 0.0f;
        vb[j] = packbf2(v, v);
    }
    uint4 xc[4], xr[4];
    #pragma unroll
    for (int j = 0; j < 4; j++) {
        xc[j] = *(const uint4*)&g_egoh[cc[j] * D + l * 8];
        xr[j] = *(const uint4*)&g_egoh[rr[j] * D + l * 8];
    }
    #pragma unroll
    for (int j = 0; j < 4; j++) {
        if (pp[j] >= half) continue;
        __nv_bfloat16* pr = &g_e2b[rr[j] * D + l * 8];
        __nv_bfloat16* pc = &g_e2b[cc[j] * D + l * 8];
        REDBF8(pr, mulbf2(vb[j], xc[j].x), mulbf2(vb[j], xc[j].y),
                   mulbf2(vb[j], xc[j].z), mulbf2(vb[j], xc[j].w));
        REDBF8(pc, mulbf2(vb[j], xr[j].x), mulbf2(vb[j], xr[j].y),
                   mulbf2(vb[j], xr[j].z), mulbf2(vb[j], xr[j].w));
    }
}

// ---------------- fused: normalize e2b -> e2h; samples -> z1/pos-dot; restore bitmap/qn ----------------
#define NORM_WARPS  N_NODES
__global__ void k_norm_sample(const int* __restrict__ nu, const int* __restrict__ ni) {
    int gw = (blockIdx.x * blockDim.x + threadIdx.x) >> 5;
    int lane = threadIdx.x & 31;
    if (gw < NORM_WARPS) {
        int w = gw;
        uint32_t u = *(const uint32_t*)&g_e2b[w * D + lane * 2];
        float2 v = __bfloat1622float2(*(__nv_bfloat162*)&u);
        float ss = v.x * v.x + v.y * v.y;
        #pragma unroll
        for (int o = 16; o; o >>= 1) ss += __shfl_xor_sync(0xffffffffu, ss, o);
        float inv = 1.0f / fmaxf(sqrtf(ss), 1e-12f);
        *(uint32_t*)&g_e2h[w * D + lane * 2] = packbf2(v.x * inv, v.y * inv);
        return;
    }
    int s = gw - NORM_WARPS;
    if (s >= 2 * BATCH) return;
    if (s == 0 && lane == 1) g_qn = 0;
    int b = s & (BATCH - 1);
    int row = (s < BATCH) ? nu[b] : (N_USERS + ni[b]);
    if (lane == 0) atomicAnd(&g_bitmap[row >> 5], ~(1u << (row & 31)));
    float2 v = *(const float2*)&g_e1[row * D + lane * 2];
    uint32_t u = *(const uint32_t*)&g_e2b[row * D + lane * 2];
    float2 w = __bfloat1622float2(*(__nv_bfloat162*)&u);
    float ss1 = v.x * v.x + v.y * v.y;
    float ss2 = w.x * w.x + w.y * w.y;
    #pragma unroll
    for (int o = 16; o; o >>= 1) {
        ss1 += __shfl_xor_sync(0xffffffffu, ss1, o);
        ss2 += __shfl_xor_sync(0xffffffffu, ss2, o);
    }
    float inv1 = 1.0f / fmaxf(sqrtf(ss1), 1e-12f);
    float inv2 = 1.0f / fmaxf(sqrtf(ss2), 1e-12f);
    float2 z1 = make_float2(v.x * inv1, v.y * inv1);
    *(uint32_t*)&g_z1h[s * D + lane * 2] = packbf2(z1.x * K2EXP, z1.y * K2EXP);
    float d = z1.x * (w.x * inv2) + z1.y * (w.y * inv2);
    #pragma unroll
    for (int o = 16; o; o >>= 1) d += __shfl_xor_sync(0xffffffffu, d, o);
    if (lane == 0) g_dot[s] = d;
}

// ---------------- mma.sync InfoNCE: BM=256, warp covers 32 rows (B fragments reused 2x) ----------------
#define SMA 0
#define SMB0 32768
#define SMB1 49152
#define SM_TOTAL 65536

__device__ __forceinline__ void ldsm4(uint32_t* r, uint32_t addr) {
    asm volatile("ldmatrix.sync.aligned.m8n8.x4.shared.b16 {%0,%1,%2,%3}, [%4];"
                 : "=r"(r[0]), "=r"(r[1]), "=r"(r[2]), "=r"(r[3]) : "r"(addr));
}
__device__ __forceinline__ void mma16816(float* c, const uint32_t* a, const uint32_t* b) {
    asm volatile(
        "mma.sync.aligned.m16n8k16.row.col.f32.bf16.bf16.f32 "
        "{%0,%1,%2,%3}, {%4,%5,%6,%7}, {%8,%9}, {%0,%1,%2,%3};"
        : "+f"(c[0]), "+f"(c[1]), "+f"(c[2]), "+f"(c[3])
        : "r"(a[0]), "r"(a[1]), "r"(a[2]), "r"(a[3]), "r"(b[0]), "r"(b[1]));
}

__global__ void __launch_bounds__(256, 2) k_nce_mma() {
    extern __shared__ char smem[];
    uint32_t sb = su32(smem);
    int tid = threadIdx.x, wid = tid >> 5, lane = tid & 31;
    int loss = blockIdx.z, mtile = blockIdx.y, chunk = blockIdx.x;
    int t0 = chunk * PER_CH;
    int t1 = t0 + PER_CH; if (t1 > NT_N) t1 = NT_N;

    // ---- load A tile: 256 rows x 64 bf16 = 32KB (1 row per thread = 8 uint4) ----
    {
        int row = tid;
        const uint4* s = (const uint4*)&g_z1h[((size_t)loss * BATCH + mtile * 256 + row) * D];
        #pragma unroll
        for (int i = 0; i < 8; i++) {
            uint32_t o = row * 128 + i * 16;
            *(uint4*)(smem + SMA + swz(o)) = s[i];
        }
    }
    __syncthreads();

    // ---- A fragments: 2 m-groups x 4 k-steps x 4 regs ----
    uint32_t afr[2][4][4];
    {
        int rowl = lane & 15;
        int hi   = (lane >> 4) & 1;
        #pragma unroll
        for (int g = 0; g < 2; g++)
            #pragma unroll
            for (int kk = 0; kk < 4; kk++) {
                uint32_t o = (wid * 32 + g * 16 + rowl) * 128 + kk * 32 + hi * 16;
                ldsm4(afr[g][kk], sb + SMA + swz(o));
            }
    }

    const __nv_bfloat16* zb = &g_e2h[(size_t)loss * N_USERS * D];
    const int boff[2] = {SMB0, SMB1};

    int brow_ld = tid >> 1;
    uint32_t bcb0 = (uint32_t)((tid & 1) * 64);
    auto loadB = [&](int t, int buf) {
        int jg = t * 128 + brow_ld;
        if (jg > NJ - 1) jg = NJ - 1;
        const char* src = (const char*)&zb[(size_t)jg * D] + bcb0;
        uint32_t dbase = sb + boff[buf];
        #pragma unroll
        for (int i = 0; i < 4; i++) {
            uint32_t o = brow_ld * 128 + bcb0 + i * 16;
            CP16(dbase + swz(o), src + i * 16);
        }
        CP_COMMIT();
    };

    int brow = lane & 7;
    uint32_t bk0 = (uint32_t)(((lane >> 3) & 3) * 16);
    uint32_t baddr0 = brow * 128 + (bk0 ^ (brow << 4));
    uint32_t baddr1 = brow * 128 + ((bk0 + 64) ^ (brow << 4));

    loadB(t0, 0);
    CP_WAIT0();
    __syncthreads();

    float s01a = 0.0f, s23a = 0.0f, s01b = 0.0f, s23b = 0.0f;
    int cur = 0;
    for (int t = t0; t < t1; ++t) {
        if (t + 1 < t1) loadB(t + 1, cur ^ 1);
        uint32_t bb = sb + boff[cur];
        int jbase = t * 128;

        if (jbase + 128 <= NJ) {
            uint32_t a01a = 0, a23a = 0, a01b = 0, a23b = 0;
            #pragma unroll 4
            for (int j = 0; j < 16; j++) {
                uint32_t bfr[8];
                ldsm4(bfr,     bb + baddr0 + j * 1024);
                ldsm4(bfr + 4, bb + baddr1 + j * 1024);
                float c[4] = {0.f, 0.f, 0.f, 0.f};
                mma16816(c, afr[0][0], bfr);
                mma16816(c, afr[0][1], bfr + 2);
                mma16816(c, afr[0][2], bfr + 4);
                mma16816(c, afr[0][3], bfr + 6);
                a01a = haddh2(a01a, ex2h2(packh2(c[1], c[0])));
                a23a = haddh2(a23a, ex2h2(packh2(c[3], c[2])));
                float e[4] = {0.f, 0.f, 0.f, 0.f};
                mma16816(e, afr[1][0], bfr);
                mma16816(e, afr[1][1], bfr + 2);
                mma16816(e, afr[1][2], bfr + 4);
                mma16816(e, afr[1][3], bfr + 6);
                a01b = haddh2(a01b, ex2h2(packh2(e[1], e[0])));
                a23b = haddh2(a23b, ex2h2(packh2(e[3], e[2])));
            }
            float2 f;
            f = __half22float2(*(__half2*)&a01a); s01a += f.x + f.y;
            f = __half22float2(*(__half2*)&a23a); s23a += f.x + f.y;
            f = __half22float2(*(__half2*)&a01b); s01b += f.x + f.y;
            f = __half22float2(*(__half2*)&a23b); s23b += f.x + f.y;
        } else {
            #pragma unroll 4
            for (int j = 0; j < 16; j++) {
                uint32_t bfr[8];
                ldsm4(bfr,     bb + baddr0 + j * 1024);
                ldsm4(bfr + 4, bb + baddr1 + j * 1024);
                float c[4] = {0.f, 0.f, 0.f, 0.f};
                mma16816(c, afr[0][0], bfr);
                mma16816(c, afr[0][1], bfr + 2);
                mma16816(c, afr[0][2], bfr + 4);
                mma16816(c, afr[0][3], bfr + 6);
                float e[4] = {0.f, 0.f, 0.f, 0.f};
                mma16816(e, afr[1][0], bfr);
                mma16816(e, afr[1][1], bfr + 2);
                mma16816(e, afr[1][2], bfr + 4);
                mma16816(e, afr[1][3], bfr + 6);
                int n0 = jbase + j * 8 + 2 * (lane & 3);
                if (n0 < NJ) {
                    s01a += exp2f(c[0]); s23a += exp2f(c[2]);
                    s01b += exp2f(e[0]); s23b += exp2f(e[2]);
                }
                if (n0 + 1 < NJ) {
                    s01a += exp2f(c[1]); s23a += exp2f(c[3]);
                    s01b += exp2f(e[1]); s23b += exp2f(e[3]);
                }
            }
        }
        if (t + 1 < t1) CP_WAIT0();
        __syncthreads();
        cur ^= 1;
    }

    #pragma unroll
    for (int o = 1; o <= 2; o <<= 1) {
        s01a += __shfl_xor_sync(0xffffffffu, s01a, o);
        s23a += __shfl_xor_sync(0xffffffffu, s23a, o);
        s01b += __shfl_xor_sync(0xffffffffu, s01b, o);
        s23b += __shfl_xor_sync(0xffffffffu, s23b, o);
    }
    if ((lane & 3) == 0) {
        int row = mtile * 256 + wid * 32 + (lane >> 2);
        atomicAdd(&g_ttl[loss * BATCH + row],      s01a);
        atomicAdd(&g_ttl[loss * BATCH + row + 8],  s23a);
        atomicAdd(&g_ttl[loss * BATCH + row + 16], s01b);
        atomicAdd(&g_ttl[loss * BATCH + row + 24], s23b);
    }
}

// ---------------- final reduction (re-zeroes g_ttl) ----------------
__global__ void k_final(float* __restrict__ out) {
    __shared__ float red[256];
    int tid = threadIdx.x;
    float s = 0.0f;
    for (int i = tid; i < 2 * BATCH; i += 256) {
        s += logf(g_ttl[i]) - 2.0f * g_dot[i];
        g_ttl[i] = 0.0f;
    }
    red[tid] = s;
    __syncthreads();
    #pragma unroll
    for (int o = 128; o; o >>= 1) {
        if (tid < o) red[tid] += red[tid + o];
        __syncthreads();
    }
    if (tid == 0) out[0] = 0.5f * red[0];
}

// ---------------- launch (2-stream fork/join, graph-capturable) ----------------
extern "C" void kernel_launch(void* const* d_in, const int* in_sizes, int n_in,
                              void* d_out, int out_size) {
    const float* ue    = (const float*)d_in[0];
    const float* ie    = (const float*)d_in[1];
    const int*   rows1 = (const int*)d_in[2];
    const int*   cols1 = (const int*)d_in[3];
    const float* vals1 = (const float*)d_in[4];
    const int*   rows2 = (const int*)d_in[5];
    const int*   cols2 = (const int*)d_in[6];
    const float* vals2 = (const float*)d_in[7];
    const int*   nu    = (const int*)d_in[8];
    const int*   ni    = (const int*)d_in[9];
    int nnz1 = in_sizes[2];
    int nnz2 = in_sizes[5];

    static cudaStream_t sB = nullptr;
    static cudaEvent_t evFork = nullptr, evInit = nullptr, evJoin = nullptr;
    if (!sB) {
        cudaStreamCreateWithFlags(&sB, cudaStreamNonBlocking);
        cudaEventCreateWithFlags(&evFork, cudaEventDisableTiming);
        cudaEventCreateWithFlags(&evInit, cudaEventDisableTiming);
        cudaEventCreateWithFlags(&evJoin, cudaEventDisableTiming);
        cudaFuncSetAttribute(k_nce_mma, cudaFuncAttributeMaxDynamicSharedMemorySize, SM_TOTAL);
    }
    cudaStream_t sA = 0;

    cudaEventRecord(evFork, sA);
    cudaStreamWaitEvent(sB, evFork, 0);

    // stream A: init -> SpMM-2 (paired)
    k_init<<<(N_NODES * D / 4 + 255) / 256, 256, 0, sA>>>(ue, ie);
    cudaEventRecord(evInit, sA);
    {
        int half = nnz2 >> 1;
        int q = (half + 3) >> 2;
        unsigned nt2 = (unsigned)q * 8u;
        k_spmm2<<<(nt2 + 255) / 256, 256, 0, sA>>>(rows2, cols2, vals2, half);
    }

    // stream B: setup(mark+e1) -> filter -> (wait egoh) -> spmm_q
    k_setup<<<(2 * BATCH * 16 + 255) / 256, 256, 0, sB>>>(ue, ie, nu, ni);
    k_filter<<<((nnz1 + 15) / 16 + 255) / 256, 256, 0, sB>>>(rows1, nnz1);
    cudaStreamWaitEvent(sB, evInit, 0);
    k_spmm_q<<<2048, 256, 0, sB>>>(rows1, cols1, vals1);
    cudaEventRecord(evJoin, sB);

    cudaStreamWaitEvent(sA, evJoin, 0);
    {
        int warps = N_NODES + 2 * BATCH;
        k_norm_sample<<<(warps * 32 + 255) / 256, 256, 0, sA>>>(nu, ni);
    }
    dim3 grid(NCH, 8, 2);
    k_nce_mma<<<grid, 256, SM_TOTAL, sA>>>();
    k_final<<<1, 256, 0, sA>>>((float*)d_out);
}

// round 17
// speedup vs baseline: 1.1484x; 1.1484x over previous
#include <cuda_runtime.h>
#include <cuda_bf16.h>
#include <cuda_fp16.h>
#include <cstdint>
#include <math.h>

#define N_USERS 50000
#define N_NODES 100000
#define D       64
#define BATCH   2048
#define NJ      50000
#define NT_N    ((NJ + 127) / 128)
#define NCH     13                           // 13*16*2 = 416 blocks = one wave @ 3 blocks/SM
#define PER_CH  ((NT_N + NCH - 1) / NCH)     // 31
#define NCE_BLOCKS (NCH * 16 * 2)            // 416
#define K2EXP   2.885390081777927f           // 2/ln(2)

// ---------------- device scratch (zero-init; invariants restored every run) ----------------
__device__ __align__(16) __nv_bfloat16 g_egoh[N_NODES * D];
__device__ __align__(16) float g_e1 [N_NODES * D];
__device__ __align__(16) __nv_bfloat16 g_e2b[N_NODES * D];
__device__ __align__(16) __nv_bfloat16 g_e2h[N_NODES * D];
__device__ __align__(16) __nv_bfloat16 g_z1h[2 * BATCH * D];
__device__ float g_dot[2 * BATCH];
__device__ float g_ttl[2 * BATCH];            // zeroed by last NCE block
__device__ unsigned g_bitmap[(N_NODES + 31) / 32];  // cleared by k_norm_sample
__device__ int g_qn;                          // reset by k_norm_sample
__device__ int g_done;                        // NCE completion counter; reset by last block
__device__ int g_queue[2000000];

__device__ __forceinline__ uint32_t swz(uint32_t o) { return o ^ ((o >> 3) & 0x70); }
__device__ __forceinline__ uint32_t su32(const void* p) {
    uint32_t a;
    asm("{ .reg .u64 t; cvta.to.shared.u64 t, %1; cvt.u32.u64 %0, t; }" : "=r"(a) : "l"(p));
    return a;
}
__device__ __forceinline__ uint32_t packh2(float hi, float lo) {
    uint32_t r; asm("cvt.rn.f16x2.f32 %0, %1, %2;" : "=r"(r) : "f"(hi), "f"(lo)); return r;
}
__device__ __forceinline__ uint32_t ex2h2(uint32_t x) {
    uint32_t r; asm("ex2.approx.f16x2 %0, %1;" : "=r"(r) : "r"(x)); return r;
}
__device__ __forceinline__ uint32_t haddh2(uint32_t a, uint32_t b) {
    uint32_t r; asm("add.rn.f16x2 %0, %1, %2;" : "=r"(r) : "r"(a), "r"(b)); return r;
}
__device__ __forceinline__ uint32_t packbf2(float lo, float hi) {
    __nv_bfloat162 h = __float22bfloat162_rn(make_float2(lo, hi));
    return *(uint32_t*)&h;
}
__device__ __forceinline__ uint32_t mulbf2(uint32_t a, uint32_t b) {
    uint32_t r; asm("mul.rn.bf16x2 %0, %1, %2;" : "=r"(r) : "r"(a), "r"(b)); return r;
}
__device__ __forceinline__ float4 gatherh(int node, int l) {
    uint2 u = *(const uint2*)&g_egoh[node * D + l * 4];
    float2 fa = __bfloat1622float2(*(__nv_bfloat162*)&u.x);
    float2 fb = __bfloat1622float2(*(__nv_bfloat162*)&u.y);
    return make_float4(fa.x, fa.y, fb.x, fb.y);
}
#define CP16(dst, src) \
    asm volatile("cp.async.ca.shared.global [%0], [%1], 16;" :: "r"(dst), "l"(src))
#define CP_COMMIT() asm volatile("cp.async.commit_group;")
#define CP_WAIT0()  asm volatile("cp.async.wait_group 0;")
#define REDV4(p, a, b, c, d) \
    asm volatile("red.global.add.v4.f32 [%0], {%1,%2,%3,%4};" \
                 :: "l"(p), "f"(a), "f"(b), "f"(c), "f"(d) : "memory")
#define REDBF8(p, r0, r1, r2, r3) \
    asm volatile("red.global.add.noftz.v4.bf16x2 [%0], {%1,%2,%3,%4};" \
                 :: "l"(p), "r"(r0), "r"(r1), "r"(r2), "r"(r3) : "memory")

// ---------------- setup: seed e1 at sampled rows + mark bitmap ----------------
__global__ void k_setup(const float* __restrict__ ue, const float* __restrict__ ie,
                        const int* __restrict__ nu, const int* __restrict__ ni) {
    int t = blockIdx.x * blockDim.x + threadIdx.x;
    int s = t >> 4, l = t & 15;
    if (s >= 2 * BATCH) return;
    int b = s & (BATCH - 1);
    int row; const float* src;
    if (s < BATCH) { row = nu[b];                 src = &ue[(size_t)row * D]; }
    else           { int r = ni[b]; row = N_USERS + r; src = &ie[(size_t)r * D]; }
    if (l == 0) atomicOr(&g_bitmap[row >> 5], 1u << (row & 31));
    float4 v = *(const float4*)&src[l * 4];
    *(float4*)&g_e1[(size_t)row * D + l * 4] =
        make_float4(0.5f * v.x, 0.5f * v.y, 0.5f * v.z, 0.5f * v.w);
}

// ---------------- init: g_e2b = bf16(0.5*ego), g_egoh = bf16(ego) ----------------
__global__ void k_init(const float* __restrict__ ue, const float* __restrict__ ie) {
    int i = blockIdx.x * blockDim.x + threadIdx.x;
    if (i >= N_NODES * D / 4) return;
    float4 v = (i < N_USERS * D / 4) ? ((const float4*)ue)[i]
                                     : ((const float4*)ie)[i - N_USERS * D / 4];
    uint2 h;
    h.x = packbf2(v.x, v.y);
    h.y = packbf2(v.z, v.w);
    ((uint2*)g_egoh)[i] = h;
    uint2 e;
    e.x = packbf2(0.5f * v.x, 0.5f * v.y);
    e.y = packbf2(0.5f * v.z, 0.5f * v.w);
    ((uint2*)g_e2b)[i] = e;
}

// ---------------- filtered SpMM-1: 16 edges/thread filter ----------------
__global__ void k_filter(const int* __restrict__ rows, int nnz) {
    int i0 = (blockIdx.x * blockDim.x + threadIdx.x) * 16;
    int lane = threadIdx.x & 31;
    int ids[16];
    int cnt = 0;
    if (i0 + 15 < nnz) {
        int4 ra = *(const int4*)&rows[i0];
        int4 rb = *(const int4*)&rows[i0 + 4];
        int4 rc = *(const int4*)&rows[i0 + 8];
        int4 rd = *(const int4*)&rows[i0 + 12];
        int rr[16] = {ra.x, ra.y, ra.z, ra.w, rb.x, rb.y, rb.z, rb.w,
                      rc.x, rc.y, rc.z, rc.w, rd.x, rd.y, rd.z, rd.w};
        #pragma unroll
        for (int j = 0; j < 16; j++)
            if ((g_bitmap[rr[j] >> 5] >> (rr[j] & 31)) & 1u) ids[cnt++] = i0 + j;
    } else {
        for (int j = 0; j < 16 && i0 + j < nnz; j++) {
            int rr = rows[i0 + j];
            if ((g_bitmap[rr >> 5] >> (rr & 31)) & 1u) ids[cnt++] = i0 + j;
        }
    }
    int x = cnt;
    #pragma unroll
    for (int o = 1; o < 32; o <<= 1) {
        int y = __shfl_up_sync(0xffffffffu, x, o);
        if (lane >= o) x += y;
    }
    int pre = x - cnt;
    int total = __shfl_sync(0xffffffffu, x, 31);
    int base = 0;
    if (lane == 31 && total) base = atomicAdd(&g_qn, total);
    base = __shfl_sync(0xffffffffu, base, 31);
    for (int j = 0; j < cnt; j++) g_queue[base + pre + j] = ids[j];
}

__global__ void k_spmm_q(const int* __restrict__ rows, const int* __restrict__ cols,
                         const float* __restrict__ vals) {
    int total = g_qn * 16;
    for (int t = blockIdx.x * blockDim.x + threadIdx.x; t < total;
         t += gridDim.x * blockDim.x) {
        int e = g_queue[t >> 4];
        int l = t & 15;
        int r = rows[e], c = cols[e];
        float v = 0.5f * vals[e];
        float4 x = gatherh(c, l);
        float* p = &g_e1[r * D + l * 4];
        REDV4(p, v * x.x, v * x.y, v * x.z, v * x.w);
    }
}

// ---------------- SpMM-2: interaction-paired, 8 lanes/interaction, v4.bf16x2 REDs ----------------
__global__ void k_spmm2(const int* __restrict__ rows, const int* __restrict__ cols,
                        const float* __restrict__ vals, int half) {
    unsigned t = blockIdx.x * blockDim.x + threadIdx.x;
    int q = (half + 3) >> 2;
    int p0 = (int)(t >> 3);
    int l = (int)(t & 7);
    if (p0 >= q) return;

    int pp[4] = {p0, p0 + q, p0 + 2 * q, p0 + 3 * q};
    int rr[4], cc[4];
    uint32_t vb[4];
    #pragma unroll
    for (int j = 0; j < 4; j++) {
        bool ok = pp[j] < half;
        int e = ok ? pp[j] : 0;
        rr[j] = __ldg(&rows[e]);
        cc[j] = __ldg(&cols[e]);
        float v = ok ? 0.5f * __ldg(&vals[e]) : 0.0f;
        vb[j] = packbf2(v, v);
    }
    uint4 xc[4], xr[4];
    #pragma unroll
    for (int j = 0; j < 4; j++) {
        xc[j] = *(const uint4*)&g_egoh[cc[j] * D + l * 8];
        xr[j] = *(const uint4*)&g_egoh[rr[j] * D + l * 8];
    }
    #pragma unroll
    for (int j = 0; j < 4; j++) {
        if (pp[j] >= half) continue;
        __nv_bfloat16* pr = &g_e2b[rr[j] * D + l * 8];
        __nv_bfloat16* pc = &g_e2b[cc[j] * D + l * 8];
        REDBF8(pr, mulbf2(vb[j], xc[j].x), mulbf2(vb[j], xc[j].y),
                   mulbf2(vb[j], xc[j].z), mulbf2(vb[j], xc[j].w));
        REDBF8(pc, mulbf2(vb[j], xr[j].x), mulbf2(vb[j], xr[j].y),
                   mulbf2(vb[j], xr[j].z), mulbf2(vb[j], xr[j].w));
    }
}

// ---------------- fused: normalize e2b -> e2h; samples -> z1/pos-dot; restore bitmap/qn ----------------
#define NORM_WARPS  N_NODES
__global__ void k_norm_sample(const int* __restrict__ nu, const int* __restrict__ ni) {
    int gw = (blockIdx.x * blockDim.x + threadIdx.x) >> 5;
    int lane = threadIdx.x & 31;
    if (gw < NORM_WARPS) {
        int w = gw;
        uint32_t u = *(const uint32_t*)&g_e2b[w * D + lane * 2];
        float2 v = __bfloat1622float2(*(__nv_bfloat162*)&u);
        float ss = v.x * v.x + v.y * v.y;
        #pragma unroll
        for (int o = 16; o; o >>= 1) ss += __shfl_xor_sync(0xffffffffu, ss, o);
        float inv = 1.0f / fmaxf(sqrtf(ss), 1e-12f);
        *(uint32_t*)&g_e2h[w * D + lane * 2] = packbf2(v.x * inv, v.y * inv);
        return;
    }
    int s = gw - NORM_WARPS;
    if (s >= 2 * BATCH) return;
    if (s == 0 && lane == 1) g_qn = 0;
    int b = s & (BATCH - 1);
    int row = (s < BATCH) ? nu[b] : (N_USERS + ni[b]);
    if (lane == 0) atomicAnd(&g_bitmap[row >> 5], ~(1u << (row & 31)));
    float2 v = *(const float2*)&g_e1[row * D + lane * 2];
    uint32_t u = *(const uint32_t*)&g_e2b[row * D + lane * 2];
    float2 w = __bfloat1622float2(*(__nv_bfloat162*)&u);
    float ss1 = v.x * v.x + v.y * v.y;
    float ss2 = w.x * w.x + w.y * w.y;
    #pragma unroll
    for (int o = 16; o; o >>= 1) {
        ss1 += __shfl_xor_sync(0xffffffffu, ss1, o);
        ss2 += __shfl_xor_sync(0xffffffffu, ss2, o);
    }
    float inv1 = 1.0f / fmaxf(sqrtf(ss1), 1e-12f);
    float inv2 = 1.0f / fmaxf(sqrtf(ss2), 1e-12f);
    float2 z1 = make_float2(v.x * inv1, v.y * inv1);
    *(uint32_t*)&g_z1h[s * D + lane * 2] = packbf2(z1.x * K2EXP, z1.y * K2EXP);
    float d = z1.x * (w.x * inv2) + z1.y * (w.y * inv2);
    #pragma unroll
    for (int o = 16; o; o >>= 1) d += __shfl_xor_sync(0xffffffffu, d, o);
    if (lane == 0) g_dot[s] = d;
}

// ---------------- mma.sync InfoNCE (3 blocks/SM) + fused last-block final reduction ----------------
#define SMA 0
#define SMB0 16384
#define SMB1 32768
#define SM_TOTAL 49152

__device__ __forceinline__ void ldsm4(uint32_t* r, uint32_t addr) {
    asm volatile("ldmatrix.sync.aligned.m8n8.x4.shared.b16 {%0,%1,%2,%3}, [%4];"
                 : "=r"(r[0]), "=r"(r[1]), "=r"(r[2]), "=r"(r[3]) : "r"(addr));
}
__device__ __forceinline__ void mma16816(float* c, const uint32_t* a, const uint32_t* b) {
    asm volatile(
        "mma.sync.aligned.m16n8k16.row.col.f32.bf16.bf16.f32 "
        "{%0,%1,%2,%3}, {%4,%5,%6,%7}, {%8,%9}, {%0,%1,%2,%3};"
        : "+f"(c[0]), "+f"(c[1]), "+f"(c[2]), "+f"(c[3])
        : "r"(a[0]), "r"(a[1]), "r"(a[2]), "r"(a[3]), "r"(b[0]), "r"(b[1]));
}

__global__ void __launch_bounds__(256, 3) k_nce_mma(float* __restrict__ out) {
    extern __shared__ char smem[];
    uint32_t sb = su32(smem);
    int tid = threadIdx.x, wid = tid >> 5, lane = tid & 31;
    int loss = blockIdx.z, mtile = blockIdx.y, chunk = blockIdx.x;
    int t0 = chunk * PER_CH;
    int t1 = t0 + PER_CH; if (t1 > NT_N) t1 = NT_N;

    {
        int row = tid >> 1;
        int cb0 = (tid & 1) * 64;
        const uint4* s = (const uint4*)&g_z1h[((size_t)loss * BATCH + mtile * 128 + row) * D];
        #pragma unroll
        for (int i = 0; i < 4; i++) {
            uint32_t o = row * 128 + cb0 + i * 16;
            *(uint4*)(smem + SMA + swz(o)) = s[(cb0 >> 4) + i];
        }
    }
    __syncthreads();

    uint32_t afr[4][4];
    {
        int rowl = lane & 15;
        int hi   = (lane >> 4) & 1;
        #pragma unroll
        for (int kk = 0; kk < 4; kk++) {
            uint32_t o = (wid * 16 + rowl) * 128 + kk * 32 + hi * 16;
            ldsm4(afr[kk], sb + SMA + swz(o));
        }
    }

    const __nv_bfloat16* zb = &g_e2h[(size_t)loss * N_USERS * D];
    const int boff[2] = {SMB0, SMB1};

    int brow_ld = tid >> 1;
    uint32_t bcb0 = (uint32_t)((tid & 1) * 64);
    auto loadB = [&](int t, int buf) {
        int jg = t * 128 + brow_ld;
        if (jg > NJ - 1) jg = NJ - 1;
        const char* src = (const char*)&zb[(size_t)jg * D] + bcb0;
        uint32_t dbase = sb + boff[buf];
        #pragma unroll
        for (int i = 0; i < 4; i++) {
            uint32_t o = brow_ld * 128 + bcb0 + i * 16;
            CP16(dbase + swz(o), src + i * 16);
        }
        CP_COMMIT();
    };

    int brow = lane & 7;
    uint32_t bk0 = (uint32_t)(((lane >> 3) & 3) * 16);
    uint32_t baddr0 = brow * 128 + (bk0 ^ (brow << 4));
    uint32_t baddr1 = brow * 128 + ((bk0 + 64) ^ (brow << 4));

    loadB(t0, 0);
    CP_WAIT0();
    __syncthreads();

    float s0 = 0.0f, s1 = 0.0f;
    int cur = 0;
    for (int t = t0; t < t1; ++t) {
        if (t + 1 < t1) loadB(t + 1, cur ^ 1);
        uint32_t bb = sb + boff[cur];
        int jbase = t * 128;

        if (jbase + 128 <= NJ) {
            uint32_t acc01 = 0, acc23 = 0;
            #pragma unroll 4
            for (int j = 0; j < 16; j++) {
                uint32_t bfr[8];
                ldsm4(bfr,     bb + baddr0 + j * 1024);
                ldsm4(bfr + 4, bb + baddr1 + j * 1024);
                float c[4] = {0.f, 0.f, 0.f, 0.f};
                mma16816(c, afr[0], bfr);
                mma16816(c, afr[1], bfr + 2);
                mma16816(c, afr[2], bfr + 4);
                mma16816(c, afr[3], bfr + 6);
                acc01 = haddh2(acc01, ex2h2(packh2(c[1], c[0])));
                acc23 = haddh2(acc23, ex2h2(packh2(c[3], c[2])));
            }
            float2 f01 = __half22float2(*(__half2*)&acc01);
            float2 f23 = __half22float2(*(__half2*)&acc23);
            s0 += f01.x + f01.y;
            s1 += f23.x + f23.y;
        } else {
            #pragma unroll 4
            for (int j = 0; j < 16; j++) {
                uint32_t bfr[8];
                ldsm4(bfr,     bb + baddr0 + j * 1024);
                ldsm4(bfr + 4, bb + baddr1 + j * 1024);
                float c[4] = {0.f, 0.f, 0.f, 0.f};
                mma16816(c, afr[0], bfr);
                mma16816(c, afr[1], bfr + 2);
                mma16816(c, afr[2], bfr + 4);
                mma16816(c, afr[3], bfr + 6);
                int n0 = jbase + j * 8 + 2 * (lane & 3);
                if (n0     < NJ) { s0 += exp2f(c[0]); s1 += exp2f(c[2]); }
                if (n0 + 1 < NJ) { s0 += exp2f(c[1]); s1 += exp2f(c[3]); }
            }
        }
        if (t + 1 < t1) CP_WAIT0();
        __syncthreads();
        cur ^= 1;
    }

    #pragma unroll
    for (int o = 1; o <= 2; o <<= 1) {
        s0 += __shfl_xor_sync(0xffffffffu, s0, o);
        s1 += __shfl_xor_sync(0xffffffffu, s1, o);
    }
    if ((lane & 3) == 0) {
        int row = mtile * 128 + wid * 16 + (lane >> 2);
        atomicAdd(&g_ttl[loss * BATCH + row],     s0);
        atomicAdd(&g_ttl[loss * BATCH + row + 8], s1);
    }

    // ---- last block performs the final reduction (replaces k_final) ----
    __shared__ int isLast;
    __threadfence();
    __syncthreads();
    if (tid == 0) {
        int n = atomicAdd(&g_done, 1);
        isLast = (n == NCE_BLOCKS - 1);
    }
    __syncthreads();
    if (!isLast) return;
    if (tid == 0) g_done = 0;     // restore invariant

    __shared__ float red[256];
    float acc = 0.0f;
    for (int i = tid; i < 2 * BATCH; i += 256) {
        acc += logf(g_ttl[i]) - 2.0f * g_dot[i];
        g_ttl[i] = 0.0f;          // restore invariant
    }
    red[tid] = acc;
    __syncthreads();
    #pragma unroll
    for (int o = 128; o; o >>= 1) {
        if (tid < o) red[tid] += red[tid + o];
        __syncthreads();
    }
    if (tid == 0) out[0] = 0.5f * red[0];
}

// ---------------- launch (2-stream fork/join, graph-capturable) ----------------
extern "C" void kernel_launch(void* const* d_in, const int* in_sizes, int n_in,
                              void* d_out, int out_size) {
    const float* ue    = (const float*)d_in[0];
    const float* ie    = (const float*)d_in[1];
    const int*   rows1 = (const int*)d_in[2];
    const int*   cols1 = (const int*)d_in[3];
    const float* vals1 = (const float*)d_in[4];
    const int*   rows2 = (const int*)d_in[5];
    const int*   cols2 = (const int*)d_in[6];
    const float* vals2 = (const float*)d_in[7];
    const int*   nu    = (const int*)d_in[8];
    const int*   ni    = (const int*)d_in[9];
    int nnz1 = in_sizes[2];
    int nnz2 = in_sizes[5];

    static cudaStream_t sB = nullptr;
    static cudaEvent_t evFork = nullptr, evInit = nullptr, evJoin = nullptr;
    if (!sB) {
        cudaStreamCreateWithFlags(&sB, cudaStreamNonBlocking);
        cudaEventCreateWithFlags(&evFork, cudaEventDisableTiming);
        cudaEventCreateWithFlags(&evInit, cudaEventDisableTiming);
        cudaEventCreateWithFlags(&evJoin, cudaEventDisableTiming);
        cudaFuncSetAttribute(k_nce_mma, cudaFuncAttributeMaxDynamicSharedMemorySize, SM_TOTAL);
    }
    cudaStream_t sA = 0;

    cudaEventRecord(evFork, sA);
    cudaStreamWaitEvent(sB, evFork, 0);

    // stream A: init -> SpMM-2 (paired)
    k_init<<<(N_NODES * D / 4 + 255) / 256, 256, 0, sA>>>(ue, ie);
    cudaEventRecord(evInit, sA);
    {
        int half = nnz2 >> 1;
        int q = (half + 3) >> 2;
        unsigned nt2 = (unsigned)q * 8u;
        k_spmm2<<<(nt2 + 255) / 256, 256, 0, sA>>>(rows2, cols2, vals2, half);
    }

    // stream B: setup(mark+e1) -> filter -> (wait egoh) -> spmm_q
    k_setup<<<(2 * BATCH * 16 + 255) / 256, 256, 0, sB>>>(ue, ie, nu, ni);
    k_filter<<<((nnz1 + 15) / 16 + 255) / 256, 256, 0, sB>>>(rows1, nnz1);
    cudaStreamWaitEvent(sB, evInit, 0);
    k_spmm_q<<<1024, 256, 0, sB>>>(rows1, cols1, vals1);
    cudaEventRecord(evJoin, sB);

    cudaStreamWaitEvent(sA, evJoin, 0);
    {
        int warps = N_NODES + 2 * BATCH;
        k_norm_sample<<<(warps * 32 + 255) / 256, 256, 0, sA>>>(nu, ni);
    }
    dim3 grid(NCH, 16, 2);
    k_nce_mma<<<grid, 256, SM_TOTAL, sA>>>((float*)d_out);
}